// round 10
// baseline (speedup 1.0000x reference)
#include <cuda_runtime.h>
#include <cuda_fp16.h>
#include <cstdint>

// CRF: energy[B,T,U] = x[B,T,D] @ w[D,U] + bias + start*lb + end*rb
// GEMM M=32768 K=1024 N=128 fp32 via single-pass fp16 mma.sync.
// R10: BK=64 (16 chunks, half the syncs), 3-stage A ring with half-chunk
// interleaved LDG/CVT/STS, 2-stage cp.async.cg B, STS.128, coalesced prep.

#define M_TOT 32768
#define K_TOT 1024
#define N_TOT 128
#define T_LEN 512
#define BM 128
#define BK 64
#define NCHUNK (K_TOT / BK)   // 16
#define NTILES (M_TOT / BM)   // 256
#define NTHREADS 256

#define ROWB 144                      // 64 fp16 = 128B + 16B pad; 9 mod 8 = 1
#define TILE 18432                    // 128 * 144
// A stages 0..2, B stages 3..4
#define SM_BIAS (5 * TILE)            // 92160
#define SM_LB   (SM_BIAS + 512)
#define SM_RB   (SM_BIAS + 1024)
#define SM_TOTAL (SM_BIAS + 1536)     // 93696 (dynamic)

__device__ __forceinline__ uint32_t smem_u32(const void* p) {
    uint32_t a;
    asm("{ .reg .u64 t; cvta.to.shared.u64 t, %1; cvt.u32.u64 %0, t; }" : "=r"(a) : "l"(p));
    return a;
}

__device__ __forceinline__ void ldsm_x4(uint32_t (&r)[4], uint32_t addr) {
    asm volatile("ldmatrix.sync.aligned.m8n8.x4.shared.b16 {%0,%1,%2,%3}, [%4];"
                 : "=r"(r[0]), "=r"(r[1]), "=r"(r[2]), "=r"(r[3]) : "r"(addr));
}

__device__ __forceinline__ void mma16816(float (&c)[4], const uint32_t (&a)[4],
                                         uint32_t b0, uint32_t b1) {
    asm volatile(
        "mma.sync.aligned.m16n8k16.row.col.f32.f16.f16.f32 "
        "{%0,%1,%2,%3}, {%4,%5,%6,%7}, {%8,%9}, {%0,%1,%2,%3};"
        : "+f"(c[0]), "+f"(c[1]), "+f"(c[2]), "+f"(c[3])
        : "r"(a[0]), "r"(a[1]), "r"(a[2]), "r"(a[3]), "r"(b0), "r"(b1));
}

__device__ __forceinline__ uint32_t pk(__half a, __half b) {
    __half2 t = __halves2half2(a, b);
    return *reinterpret_cast<uint32_t*>(&t);
}

#define CP_ASYNC16(dst, src) \
    asm volatile("cp.async.cg.shared.global [%0], [%1], 16;" \
                 :: "r"((uint32_t)(dst)), "l"(src) : "memory")
#define CP_COMMIT() asm volatile("cp.async.commit_group;" ::: "memory")
#define CP_WAIT(n)  asm volatile("cp.async.wait_group %0;" :: "n"(n) : "memory")

// w transposed to [N, K] fp16 (K-major, "col" operand for mma.sync)
__device__ __align__(16) __half g_wh[N_TOT * K_TOT];

// coalesced transpose prep: 32x32 smem tiles
__global__ __launch_bounds__(256)
void prep_w_kernel(const float* __restrict__ w) {
    __shared__ __half t[32][33];
    const int tx = threadIdx.x & 31, ty0 = threadIdx.x >> 5;   // 32 x 8
    const int kb = blockIdx.x * 32, nb = blockIdx.y * 32;
#pragma unroll
    for (int j = 0; j < 4; j++) {
        int k = ty0 + j * 8;
        t[tx][k] = __float2half(w[(size_t)(kb + k) * N_TOT + nb + tx]);
    }
    __syncthreads();
#pragma unroll
    for (int j = 0; j < 4; j++) {
        int n = ty0 + j * 8;
        g_wh[(size_t)(nb + n) * K_TOT + kb + tx] = t[n][tx];
    }
}

__global__ __launch_bounds__(NTHREADS, 2)
void crf_mma_kernel(const float* __restrict__ x, const int* __restrict__ mask,
                    const float* __restrict__ bias, const float* __restrict__ lb,
                    const float* __restrict__ rb, float* __restrict__ out) {
    extern __shared__ __align__(128) char sm[];
    const uint32_t smb = smem_u32(sm);

    const int tid = threadIdx.x;
    const int wid = tid >> 5, lane = tid & 31;
    const int wm = wid & 1, wn = wid >> 1;      // 2 M-warps x 4 N-warps, 64x32
    const int rowBase = blockIdx.x * BM;

    float acc[4][4][4];
#pragma unroll
    for (int i = 0; i < 4; i++)
#pragma unroll
        for (int j = 0; j < 4; j++)
#pragma unroll
            for (int v = 0; v < 4; v++) acc[i][j][v] = 0.0f;

    const int grp = lane >> 3, lr = lane & 7;
    const uint32_t aRow = wm * 64 + (grp & 1) * 8 + lr;
    const uint32_t aKof = (grp >> 1) * 8;
    const uint32_t bRow = wn * 32 + (grp >> 1) * 8 + lr;
    const uint32_t bKof = (grp & 1) * 8;

    float4 aR[4];   // half-chunk of A (2 pairs of float4 per thread)

    auto ldgA_half = [&](int c, int h) {
        const int kt = c * BK;
#pragma unroll
        for (int i = 0; i < 2; i++) {
            int p = h * 512 + i * 256 + tid;          // 1024 pairs per chunk
            int r = p >> 3, q = p & 7;                // 8 pairs per 64-elem row
            const float* src = x + (size_t)(rowBase + r) * K_TOT + kt + q * 8;
            aR[i * 2 + 0] = *reinterpret_cast<const float4*>(src);
            aR[i * 2 + 1] = *reinterpret_cast<const float4*>(src + 4);
        }
    };
    auto stsA_half = [&](int st, int h) {
        char* base = sm + st * TILE;
#pragma unroll
        for (int i = 0; i < 2; i++) {
            int p = h * 512 + i * 256 + tid;
            int r = p >> 3, q = p & 7;
            float4 v0 = aR[i * 2 + 0], v1 = aR[i * 2 + 1];
            uint4 o;
            o.x = pk(__float2half(v0.x), __float2half(v0.y));
            o.y = pk(__float2half(v0.z), __float2half(v0.w));
            o.z = pk(__float2half(v1.x), __float2half(v1.y));
            o.w = pk(__float2half(v1.z), __float2half(v1.w));
            *(uint4*)(base + (uint32_t)(r * ROWB + q * 16)) = o;
        }
    };
    auto cpasync_B = [&](int c, int bst) {
        const int kt = c * BK;
        const uint32_t base = smb + (3 + bst) * TILE;
#pragma unroll
        for (int i = 0; i < 4; i++) {
            int idx = i * NTHREADS + tid;
            int n = idx >> 3, q = idx & 7;            // 128 rows x 8 x 16B
            CP_ASYNC16(base + (uint32_t)(n * ROWB + q * 16),
                       g_wh + (size_t)n * K_TOT + kt + q * 8);
        }
        CP_COMMIT();
    };

    // ---- prologue: B(0),B(1) async; A(0)->st0, A(1)->st1 ----
    cpasync_B(0, 0);
    cpasync_B(1, 1);
    ldgA_half(0, 0); stsA_half(0, 0);
    ldgA_half(0, 1); stsA_half(0, 1);
    ldgA_half(1, 0); stsA_half(1, 0);
    ldgA_half(1, 1); stsA_half(1, 1);
    if (tid < N_TOT) {
        *(float*)(sm + SM_BIAS + tid * 4) = bias[tid];
        *(float*)(sm + SM_LB + tid * 4) = lb[tid];
        *(float*)(sm + SM_RB + tid * 4) = rb[tid];
    }
    CP_WAIT(1);          // B(0) complete
    __syncthreads();

#pragma unroll 1
    for (int c = 0; c < NCHUNK; c++) {
        const uint32_t aSt = smb + (c % 3) * TILE;
        const uint32_t bSt = smb + (3 + (c & 1)) * TILE;
        const bool pf = (c + 2 < NCHUNK);
        const int st2 = (c + 2) % 3;

        if (pf) ldgA_half(c + 2, 0);

#pragma unroll
        for (int ks = 0; ks < 4; ks++) {
            uint32_t af[4][4];
#pragma unroll
            for (int mt = 0; mt < 4; mt++)
                ldsm_x4(af[mt], aSt + (aRow + mt * 16) * ROWB + (ks * 16 + aKof) * 2);
            uint32_t bf[2][4];
#pragma unroll
            for (int np = 0; np < 2; np++)
                ldsm_x4(bf[np], bSt + (bRow + np * 16) * ROWB + (ks * 16 + bKof) * 2);
#pragma unroll
            for (int mt = 0; mt < 4; mt++)
#pragma unroll
                for (int np = 0; np < 2; np++) {
                    mma16816(acc[mt][2 * np + 0], af[mt], bf[np][0], bf[np][1]);
                    mma16816(acc[mt][2 * np + 1], af[mt], bf[np][2], bf[np][3]);
                }
            if (ks == 1 && pf) { stsA_half(st2, 0); ldgA_half(c + 2, 1); }
            if (ks == 3 && pf) stsA_half(st2, 1);
        }

        CP_WAIT(0);                  // B(c+1) complete
        __syncthreads();
        if (pf) cpasync_B(c + 2, c & 1);
    }

    // ---- fused epilogue ----
    const float* sb = (const float*)(sm + SM_BIAS);
    const float* sl = (const float*)(sm + SM_LB);
    const float* sr = (const float*)(sm + SM_RB);
    const int colBase = wn * 32 + (lane & 3) * 2;
#pragma unroll
    for (int mt = 0; mt < 4; mt++) {
#pragma unroll
        for (int h = 0; h < 2; h++) {
            int m = rowBase + wm * 64 + mt * 16 + h * 8 + (lane >> 2);
            int bb = m >> 9, t = m & (T_LEN - 1);
            const int* mrow = mask + bb * T_LEN;
            int mv = mrow[t];
            int prev = t ? mrow[t - 1] : 0;
            int nxt = (t < T_LEN - 1) ? mrow[t + 1] : 0;
            float sf = (mv > prev) ? 1.0f : 0.0f;
            float ef = (nxt > mv) ? 1.0f : 0.0f;
            float* orow = out + (size_t)m * N_TOT;
#pragma unroll
            for (int nt = 0; nt < 4; nt++) {
                int col = colBase + nt * 8;
                float2 v;
                v.x = acc[mt][nt][h * 2 + 0] + sb[col] + sf * sl[col] + ef * sr[col];
                v.y = acc[mt][nt][h * 2 + 1] + sb[col + 1] + sf * sl[col + 1] + ef * sr[col + 1];
                *reinterpret_cast<float2*>(orow + col) = v;
            }
        }
    }
}

extern "C" void kernel_launch(void* const* d_in, const int* in_sizes, int n_in,
                              void* d_out, int out_size) {
    const float* x    = (const float*)d_in[0];  // [B,T,D]
    const int*   mask = (const int*)d_in[1];    // [B,T]
    const float* w    = (const float*)d_in[2];  // [D,U]
    const float* bias = (const float*)d_in[3];
    const float* lb   = (const float*)d_in[4];
    const float* rb   = (const float*)d_in[5];
    float* out = (float*)d_out;

    dim3 pg(K_TOT / 32, N_TOT / 32);
    prep_w_kernel<<<pg, 256>>>(w);

    static int configured = 0;
    if (!configured) {
        cudaFuncSetAttribute(crf_mma_kernel,
                             cudaFuncAttributeMaxDynamicSharedMemorySize, SM_TOTAL);
        configured = 1;
    }
    crf_mma_kernel<<<NTILES, NTHREADS, SM_TOTAL>>>(x, mask, bias, lb, rb, out);
}

// round 11
// speedup vs baseline: 1.1328x; 1.1328x over previous
#include <cuda_runtime.h>
#include <cuda_fp16.h>
#include <cstdint>

// CRF: energy[B,T,U] = x[B,T,D] @ w[D,U] + bias + start*lb + end*rb
// GEMM M=32768 K=1024 N=128 fp32 via single-pass fp16 mma.sync.
// R11 = R9 main kernel (best: 40.3us) + R10 coalesced prep (-3us overhead)
//       + __ldcs evict-first on the single-use x stream.

#define M_TOT 32768
#define K_TOT 1024
#define N_TOT 128
#define T_LEN 512
#define BM 128
#define BK 32
#define NCHUNK (K_TOT / BK)   // 32
#define NTILES (M_TOT / BM)   // 256
#define NTHREADS 256

#define ROWB 80                       // row stride; ldmatrix conflict-free
#define TILE_BYTES (128 * ROWB)       // 10240
#define A_OFF 0
#define B_OFF TILE_BYTES
#define BUF_STRIDE (2 * TILE_BYTES)   // 20480
#define SM_BIAS (2 * BUF_STRIDE)      // 40960
#define SM_LB   (SM_BIAS + 512)
#define SM_RB   (SM_BIAS + 1024)
#define SM_TOTAL (SM_BIAS + 1536)     // 42496 (dynamic)

__device__ __forceinline__ uint32_t smem_u32(const void* p) {
    uint32_t a;
    asm("{ .reg .u64 t; cvta.to.shared.u64 t, %1; cvt.u32.u64 %0, t; }" : "=r"(a) : "l"(p));
    return a;
}

__device__ __forceinline__ void ldsm_x4(uint32_t (&r)[4], uint32_t addr) {
    asm volatile("ldmatrix.sync.aligned.m8n8.x4.shared.b16 {%0,%1,%2,%3}, [%4];"
                 : "=r"(r[0]), "=r"(r[1]), "=r"(r[2]), "=r"(r[3]) : "r"(addr));
}

__device__ __forceinline__ void mma16816(float (&c)[4], const uint32_t (&a)[4],
                                         uint32_t b0, uint32_t b1) {
    asm volatile(
        "mma.sync.aligned.m16n8k16.row.col.f32.f16.f16.f32 "
        "{%0,%1,%2,%3}, {%4,%5,%6,%7}, {%8,%9}, {%0,%1,%2,%3};"
        : "+f"(c[0]), "+f"(c[1]), "+f"(c[2]), "+f"(c[3])
        : "r"(a[0]), "r"(a[1]), "r"(a[2]), "r"(a[3]), "r"(b0), "r"(b1));
}

__device__ __forceinline__ uint32_t pk(__half a, __half b) {
    __half2 t = __halves2half2(a, b);
    return *reinterpret_cast<uint32_t*>(&t);
}

#define CP_ASYNC16(dst, src) \
    asm volatile("cp.async.cg.shared.global [%0], [%1], 16;" \
                 :: "r"((uint32_t)(dst)), "l"(src) : "memory")
#define CP_COMMIT() asm volatile("cp.async.commit_group;" ::: "memory")
#define CP_WAIT(n)  asm volatile("cp.async.wait_group %0;" :: "n"(n) : "memory")

// w transposed to [N, K] fp16 (K-major, "col" operand for mma.sync)
__device__ __align__(16) __half g_wh[N_TOT * K_TOT];

// coalesced transpose prep: 32x32 smem tiles (R10, verified)
__global__ __launch_bounds__(256)
void prep_w_kernel(const float* __restrict__ w) {
    __shared__ __half t[32][33];
    const int tx = threadIdx.x & 31, ty0 = threadIdx.x >> 5;   // 32 x 8
    const int kb = blockIdx.x * 32, nb = blockIdx.y * 32;
#pragma unroll
    for (int j = 0; j < 4; j++) {
        int k = ty0 + j * 8;
        t[tx][k] = __float2half(w[(size_t)(kb + k) * N_TOT + nb + tx]);
    }
    __syncthreads();
#pragma unroll
    for (int j = 0; j < 4; j++) {
        int n = ty0 + j * 8;
        g_wh[(size_t)(nb + n) * K_TOT + kb + tx] = t[n][tx];
    }
}

__global__ __launch_bounds__(NTHREADS, 2)
void crf_mma_kernel(const float* __restrict__ x, const int* __restrict__ mask,
                    const float* __restrict__ bias, const float* __restrict__ lb,
                    const float* __restrict__ rb, float* __restrict__ out) {
    extern __shared__ __align__(128) char sm[];
    const uint32_t smb = smem_u32(sm);

    const int tid = threadIdx.x;
    const int wid = tid >> 5, lane = tid & 31;
    const int wm = wid & 1, wn = wid >> 1;      // 2 M-warps x 4 N-warps, tile 64x32
    const int rowBase = blockIdx.x * BM;

    if (tid < N_TOT) {
        *(float*)(sm + SM_BIAS + tid * 4) = bias[tid];
        *(float*)(sm + SM_LB + tid * 4) = lb[tid];
        *(float*)(sm + SM_RB + tid * 4) = rb[tid];
    }

    float acc[4][4][4];   // [mt][nt][frag]
#pragma unroll
    for (int i = 0; i < 4; i++)
#pragma unroll
        for (int j = 0; j < 4; j++)
#pragma unroll
            for (int v = 0; v < 4; v++) acc[i][j][v] = 0.0f;

    const int grp = lane >> 3, lr = lane & 7;
    const uint32_t aRow = wm * 64 + (grp & 1) * 8 + lr;
    const uint32_t aKof = (grp >> 1) * 8;
    const uint32_t bRow = wn * 32 + (grp >> 1) * 8 + lr;
    const uint32_t bKof = (grp & 1) * 8;

    float4 aR[4];

    auto load_regs = [&](int c) {       // A chunk -> regs (2 ahead), evict-first
        const int kt = c * BK;
#pragma unroll
        for (int i = 0; i < 4; i++) {
            int idx = i * NTHREADS + tid;
            int r = idx >> 3, c4 = idx & 7;          // 128 rows x 8 float4
            aR[i] = __ldcs(reinterpret_cast<const float4*>(
                x + (size_t)(rowBase + r) * K_TOT + kt + c4 * 4));
        }
    };
    auto sts_A = [&](int buf) {         // convert + store A
        char* base = sm + buf * BUF_STRIDE;
#pragma unroll
        for (int i = 0; i < 4; i++) {
            int idx = i * NTHREADS + tid;
            int r = idx >> 3, c4 = idx & 7;
            float4 v = aR[i];
            uint2 hh;
            hh.x = pk(__float2half(v.x), __float2half(v.y));
            hh.y = pk(__float2half(v.z), __float2half(v.w));
            *(uint2*)(base + A_OFF + (uint32_t)(r * ROWB + c4 * 8)) = hh;
        }
    };
    auto cpasync_B = [&](int c, int buf) {   // B chunk -> smem via cp.async
        const int kt = c * BK;
        const uint32_t base = smb + buf * BUF_STRIDE + B_OFF;
#pragma unroll
        for (int i = 0; i < 2; i++) {
            int idx = i * NTHREADS + tid;
            int n = idx >> 2, q = idx & 3;           // 128 rows x 4 x 16B
            CP_ASYNC16(base + (uint32_t)(n * ROWB + q * 16),
                       g_wh + (size_t)n * K_TOT + kt + q * 8);
        }
        CP_COMMIT();
    };

    // ---- prologue ----
    load_regs(0);
    cpasync_B(0, 0);
    sts_A(0);          // into buf 0 (sts_A uses aR = chunk 0)
    load_regs(1);
    cpasync_B(1, 1);
    CP_WAIT(1);        // B(0) arrived; B(1) still in flight
    __syncthreads();

#pragma unroll 1
    for (int c = 0; c < NCHUNK; c++) {
        const uint32_t cb = smb + (c & 1) * BUF_STRIDE;
        if (c + 1 < NCHUNK) sts_A((c + 1) & 1);      // aR holds A(c+1)
        if (c + 2 < NCHUNK) load_regs(c + 2);

        // ---- compute chunk c: 2 k16-steps ----
#pragma unroll
        for (int ks = 0; ks < 2; ks++) {
            uint32_t af[4][4];
#pragma unroll
            for (int mt = 0; mt < 4; mt++)
                ldsm_x4(af[mt], cb + A_OFF + (aRow + mt * 16) * ROWB + (ks * 16 + aKof) * 2);
            uint32_t bf[2][4];
#pragma unroll
            for (int np = 0; np < 2; np++)
                ldsm_x4(bf[np], cb + B_OFF + (bRow + np * 16) * ROWB + (ks * 16 + bKof) * 2);
#pragma unroll
            for (int mt = 0; mt < 4; mt++)
#pragma unroll
                for (int np = 0; np < 2; np++) {
                    mma16816(acc[mt][2 * np + 0], af[mt], bf[np][0], bf[np][1]);
                    mma16816(acc[mt][2 * np + 1], af[mt], bf[np][2], bf[np][3]);
                }
        }

        CP_WAIT(0);          // B(c+1) complete before flipping buffers
        __syncthreads();
        if (c + 2 < NCHUNK) cpasync_B(c + 2, c & 1);   // refill freed buffer
    }

    // ---- fused epilogue ----
    const float* sb = (const float*)(sm + SM_BIAS);
    const float* sl = (const float*)(sm + SM_LB);
    const float* sr = (const float*)(sm + SM_RB);
    const int colBase = wn * 32 + (lane & 3) * 2;
#pragma unroll
    for (int mt = 0; mt < 4; mt++) {
#pragma unroll
        for (int h = 0; h < 2; h++) {
            int m = rowBase + wm * 64 + mt * 16 + h * 8 + (lane >> 2);
            int bb = m >> 9, t = m & (T_LEN - 1);
            const int* mrow = mask + bb * T_LEN;
            int mv = mrow[t];
            int prev = t ? mrow[t - 1] : 0;
            int nxt = (t < T_LEN - 1) ? mrow[t + 1] : 0;
            float sf = (mv > prev) ? 1.0f : 0.0f;
            float ef = (nxt > mv) ? 1.0f : 0.0f;
            float* orow = out + (size_t)m * N_TOT;
#pragma unroll
            for (int nt = 0; nt < 4; nt++) {
                int col = colBase + nt * 8;
                float2 v;
                v.x = acc[mt][nt][h * 2 + 0] + sb[col] + sf * sl[col] + ef * sr[col];
                v.y = acc[mt][nt][h * 2 + 1] + sb[col + 1] + sf * sl[col + 1] + ef * sr[col + 1];
                *reinterpret_cast<float2*>(orow + col) = v;
            }
        }
    }
}

extern "C" void kernel_launch(void* const* d_in, const int* in_sizes, int n_in,
                              void* d_out, int out_size) {
    const float* x    = (const float*)d_in[0];  // [B,T,D]
    const int*   mask = (const int*)d_in[1];    // [B,T]
    const float* w    = (const float*)d_in[2];  // [D,U]
    const float* bias = (const float*)d_in[3];
    const float* lb   = (const float*)d_in[4];
    const float* rb   = (const float*)d_in[5];
    float* out = (float*)d_out;

    dim3 pg(K_TOT / 32, N_TOT / 32);
    prep_w_kernel<<<pg, 256>>>(w);

    static int configured = 0;
    if (!configured) {
        cudaFuncSetAttribute(crf_mma_kernel,
                             cudaFuncAttributeMaxDynamicSharedMemorySize, SM_TOTAL);
        configured = 1;
    }
    crf_mma_kernel<<<NTILES, NTHREADS, SM_TOTAL>>>(x, mask, bias, lb, rb, out);
}